// round 5
// baseline (speedup 1.0000x reference)
#include <cuda_runtime.h>

#define NN 50000
#define EE 800000
#define F 64
#define GG 64
#define CC 10
#define NBLK 49   // ceil(NN/1024)

typedef unsigned long long ull;

// ---------------- scratch (device globals; no allocation allowed) ----------------
// zero-region: [wdeg: NN floats][degcnt: NN ints][scan state: NBLK ull]
#define WDEG_OFF   0
#define DEGCNT_OFF (NN * 4)
#define STATE_OFF  (2 * NN * 4)
#define ZERO_BYTES (STATE_OFF + 64 * 8)
__device__ __align__(16) unsigned char g_zero[ZERO_BYTES];

__device__ __align__(16) float g_dinv[NN];
__device__ __align__(16) int   g_rowptr[NN + 1];
__device__ __align__(16) int   g_fill[NN];
__device__ __align__(16) int2  g_edges[EE];      // (col, bitcast(norm)) sorted by row
__device__ __align__(16) float g_T1[NN * F];
__device__ __align__(16) float g_H0[NN * F];
__device__ __align__(16) float g_H1[NN * F];
__device__ __align__(16) float g_pool[GG * F];

// ---------------- packed f32x2 helpers ----------------
__device__ __forceinline__ void fma2(ull& d, ull a, ull b) {
    asm("fma.rn.f32x2 %0, %1, %2, %0;" : "+l"(d) : "l"(a), "l"(b));
}
__device__ __forceinline__ ull pk2(float lo, float hi) {
    ull r;
    asm("mov.b64 %0, {%1, %2};" : "=l"(r) : "f"(lo), "f"(hi));
    return r;
}
__device__ __forceinline__ float2 unpk2(ull v) {
    float2 r;
    asm("mov.b64 {%0, %1}, %2;" : "=f"(r.x), "=f"(r.y) : "l"(v));
    return r;
}

// ---------------- build ----------------
__global__ void deg_kernel(const int* __restrict__ ei, const float* __restrict__ attr) {
    float* wdeg = (float*)(g_zero + WDEG_OFF);
    int* degcnt = (int*)(g_zero + DEGCNT_OFF);
    int e = blockIdx.x * blockDim.x + threadIdx.x;
    if (e < EE) {
        int r = ei[e];
        atomicAdd(&wdeg[r], attr[e]);
        atomicAdd(&degcnt[r], 1);
    }
}

// Single-kernel scan: block-local scan + publish partial + sum-all-predecessors.
// Fuses dinv, rowptr, fill init. 49 blocks x 1024 (all resident in wave 1).
__global__ void scan_kernel() {
    float* wdeg = (float*)(g_zero + WDEG_OFF);
    int* degcnt = (int*)(g_zero + DEGCNT_OFF);
    volatile ull* state = (volatile ull*)(g_zero + STATE_OFF);

    int tid = threadIdx.x;
    int b = blockIdx.x;
    int i = b * 1024 + tid;
    int v = (i < NN) ? degcnt[i] : 0;

    if (i < NN) {
        float d = wdeg[i];
        g_dinv[i] = (d > 0.f) ? rsqrtf(d) : 0.f;
    }

    int lane = tid & 31, wid = tid >> 5;
    int x = v;
    #pragma unroll
    for (int o = 1; o < 32; o <<= 1) {
        int y = __shfl_up_sync(0xFFFFFFFFu, x, o);
        if (lane >= o) x += y;
    }
    __shared__ int ws[32];
    __shared__ int s_prefix;
    if (lane == 31) ws[wid] = x;
    __syncthreads();
    if (wid == 0) {
        int s = ws[lane];
        #pragma unroll
        for (int o = 1; o < 32; o <<= 1) {
            int y = __shfl_up_sync(0xFFFFFFFFu, s, o);
            if (lane >= o) s += y;
        }
        ws[lane] = s;
    }
    __syncthreads();
    int blocksum = ws[31];

    // publish partial, then sum predecessors (warp 0)
    if (tid == 0) {
        atomicExch((ull*)&state[b], (1ull << 32) | (unsigned)blocksum);
    }
    if (tid < 32) {
        int acc = 0;
        for (int p = tid; p < b; p += 32) {
            ull sv;
            do { sv = state[p]; } while ((sv >> 32) == 0);
            acc += (int)(unsigned)sv;
        }
        #pragma unroll
        for (int o = 16; o > 0; o >>= 1) acc += __shfl_down_sync(0xFFFFFFFFu, acc, o);
        if (tid == 0) s_prefix = acc;
    }
    __syncthreads();

    int excl = x - v + (wid > 0 ? ws[wid - 1] : 0);
    if (i < NN) {
        int r = excl + s_prefix;
        g_rowptr[i] = r;
        g_fill[i]   = r;
    }
    if (b == 0 && tid == 0) g_rowptr[NN] = EE;  // total edge count is constant
}

__global__ void fill_kernel(const int* __restrict__ ei, const float* __restrict__ attr) {
    int e = blockIdx.x * blockDim.x + threadIdx.x;
    if (e < EE) {
        int r = ei[e];
        int c = ei[EE + e];
        float w = -attr[e] * g_dinv[r] * g_dinv[c];
        int pos = atomicAdd(&g_fill[r], 1);
        g_edges[pos] = make_int2(c, __float_as_int(w));
    }
}

// ---------------- prop: T1 = S * in  (warp per row, 4x unrolled gather) ----------------
__global__ void prop_kernel(const float* __restrict__ in, float* __restrict__ out) {
    int row = blockIdx.x * (blockDim.x >> 5) + (threadIdx.x >> 5);
    if (row >= NN) return;
    int lane = threadIdx.x & 31;
    int s = g_rowptr[row], e = g_rowptr[row + 1];
    const float2* in2 = (const float2*)in;

    float ax = 0.f, ay = 0.f, bx = 0.f, by = 0.f;
    float cx = 0.f, cy = 0.f, dx = 0.f, dy = 0.f;
    int j = s;
    for (; j + 4 <= e; j += 4) {
        int2 e0 = g_edges[j];
        int2 e1 = g_edges[j + 1];
        int2 e2 = g_edges[j + 2];
        int2 e3 = g_edges[j + 3];
        float2 v0 = in2[e0.x * 32 + lane];
        float2 v1 = in2[e1.x * 32 + lane];
        float2 v2 = in2[e2.x * 32 + lane];
        float2 v3 = in2[e3.x * 32 + lane];
        ax = fmaf(__int_as_float(e0.y), v0.x, ax);
        ay = fmaf(__int_as_float(e0.y), v0.y, ay);
        bx = fmaf(__int_as_float(e1.y), v1.x, bx);
        by = fmaf(__int_as_float(e1.y), v1.y, by);
        cx = fmaf(__int_as_float(e2.y), v2.x, cx);
        cy = fmaf(__int_as_float(e2.y), v2.y, cy);
        dx = fmaf(__int_as_float(e3.y), v3.x, dx);
        dy = fmaf(__int_as_float(e3.y), v3.y, dy);
    }
    for (; j < e; j++) {
        int2 ed = g_edges[j];
        float2 v = in2[ed.x * 32 + lane];
        ax = fmaf(__int_as_float(ed.y), v.x, ax);
        ay = fmaf(__int_as_float(ed.y), v.y, ay);
    }
    float sx = (ax + bx) + (cx + dx);
    float sy = (ay + by) + (cy + dy);
    ((float2*)out)[row * 32 + lane] = make_float2(sx, sy);
}

// ---------------- fused: T2 built in smem (2*S*T1 - x0), then 3-matrix GEMM ----------------
// out = relu?(x0@W[0] + T1@W[1] + T2@W[2] + b)
// block: 64 rows x 64 cols, 256 threads (8 warps), thread tile 4x4, f32x2 FMA
template <bool RELU>
__global__ __launch_bounds__(256, 2) void gemmf_kernel(
    const float* __restrict__ x0, const float* __restrict__ x1,
    const float* __restrict__ W, const float* __restrict__ b, float* __restrict__ out) {
    extern __shared__ float smem[];
    float* sW = smem;             // 3*64*64
    float* sX0 = smem + 12288;    // 64*64
    float* sX1 = sX0 + 4096;
    float* sX2 = sX1 + 4096;
    int tid = threadIdx.x;
    int lane = tid & 31, wid = tid >> 5;
    int row0 = blockIdx.x * 64;

    // stage W (48 KB)
    {
        float4* d = (float4*)sW;
        const float4* g = (const float4*)W;
        #pragma unroll
        for (int i = tid; i < 3 * 1024; i += 256) d[i] = g[i];
    }
    // stage x0, x1 rows
    {
        const float4* g0 = (const float4*)x0;
        const float4* g1 = (const float4*)x1;
        float4* d0 = (float4*)sX0;
        float4* d1 = (float4*)sX1;
        for (int i = tid; i < 1024; i += 256) {
            int r = i >> 4, c = i & 15;
            int row = row0 + r;
            bool ok = row < NN;
            d0[i] = ok ? g0[row * 16 + c] : make_float4(0.f, 0.f, 0.f, 0.f);
            d1[i] = ok ? g1[row * 16 + c] : make_float4(0.f, 0.f, 0.f, 0.f);
        }
    }
    __syncthreads();

    // gather phase: warp w handles local rows w*8 .. w*8+7; T2 = 2*S*T1 - x0
    {
        const float2* in2 = (const float2*)x1;
        #pragma unroll
        for (int rr = 0; rr < 8; rr++) {
            int lr = wid * 8 + rr;
            int row = row0 + lr;
            if (row < NN) {
                int s = g_rowptr[row], e = g_rowptr[row + 1];
                float ax = 0.f, ay = 0.f, bx = 0.f, by = 0.f;
                float cx = 0.f, cy = 0.f, dx = 0.f, dy = 0.f;
                int j = s;
                for (; j + 4 <= e; j += 4) {
                    int2 e0 = g_edges[j];
                    int2 e1 = g_edges[j + 1];
                    int2 e2 = g_edges[j + 2];
                    int2 e3 = g_edges[j + 3];
                    float2 v0 = in2[e0.x * 32 + lane];
                    float2 v1 = in2[e1.x * 32 + lane];
                    float2 v2 = in2[e2.x * 32 + lane];
                    float2 v3 = in2[e3.x * 32 + lane];
                    ax = fmaf(__int_as_float(e0.y), v0.x, ax);
                    ay = fmaf(__int_as_float(e0.y), v0.y, ay);
                    bx = fmaf(__int_as_float(e1.y), v1.x, bx);
                    by = fmaf(__int_as_float(e1.y), v1.y, by);
                    cx = fmaf(__int_as_float(e2.y), v2.x, cx);
                    cy = fmaf(__int_as_float(e2.y), v2.y, cy);
                    dx = fmaf(__int_as_float(e3.y), v3.x, dx);
                    dy = fmaf(__int_as_float(e3.y), v3.y, dy);
                }
                for (; j < e; j++) {
                    int2 ed = g_edges[j];
                    float2 v = in2[ed.x * 32 + lane];
                    ax = fmaf(__int_as_float(ed.y), v.x, ax);
                    ay = fmaf(__int_as_float(ed.y), v.y, ay);
                }
                float sx = (ax + bx) + (cx + dx);
                float sy = (ay + by) + (cy + dy);
                float2 sub = ((const float2*)sX0)[lr * 32 + lane];
                ((float2*)sX2)[lr * 32 + lane] =
                    make_float2(2.f * sx - sub.x, 2.f * sy - sub.y);
            }
        }
    }
    __syncthreads();

    // GEMM phase
    int tc = tid & 15;   // col group (4 cols)
    int tr = tid >> 4;   // row group (4 rows)

    ull accA[4], accB[4];
    #pragma unroll
    for (int i = 0; i < 4; i++) { accA[i] = 0ull; accB[i] = 0ull; }

    const ull* wp = (const ull*)sW;  // mat m at m*2048, row k at k*32, col-pair at tc*2
    const float* X0 = sX0;
    const float* X1 = sX1;
    const float* X2 = sX2;

    #pragma unroll 4
    for (int k = 0; k < 64; k += 4) {
        float4 a0[4], a1[4], a2[4];
        #pragma unroll
        for (int i = 0; i < 4; i++) {
            int r = tr * 4 + i;
            a0[i] = *(const float4*)(X0 + r * 64 + k);
            a1[i] = *(const float4*)(X1 + r * 64 + k);
            a2[i] = *(const float4*)(X2 + r * 64 + k);
        }
        #pragma unroll
        for (int j = 0; j < 4; j++) {
            int wi = (k + j) * 32 + tc * 2;
            ull w0xy = wp[wi],        w0zw = wp[wi + 1];
            ull w1xy = wp[2048 + wi], w1zw = wp[2048 + wi + 1];
            ull w2xy = wp[4096 + wi], w2zw = wp[4096 + wi + 1];
            #pragma unroll
            for (int i = 0; i < 4; i++) {
                float p = ((const float*)&a0[i])[j];
                float q = ((const float*)&a1[i])[j];
                float t = ((const float*)&a2[i])[j];
                ull pp = pk2(p, p);
                ull qq = pk2(q, q);
                ull tt = pk2(t, t);
                fma2(accA[i], w0xy, pp);
                fma2(accB[i], w0zw, pp);
                fma2(accA[i], w1xy, qq);
                fma2(accB[i], w1zw, qq);
                fma2(accA[i], w2xy, tt);
                fma2(accB[i], w2zw, tt);
            }
        }
    }

    float4 bias = ((const float4*)b)[tc];
    #pragma unroll
    for (int i = 0; i < 4; i++) {
        int row = row0 + tr * 4 + i;
        if (row < NN) {
            float2 lo = unpk2(accA[i]);
            float2 hi = unpk2(accB[i]);
            float4 o;
            o.x = lo.x + bias.x;
            o.y = lo.y + bias.y;
            o.z = hi.x + bias.z;
            o.w = hi.y + bias.w;
            if (RELU) {
                o.x = fmaxf(o.x, 0.f); o.y = fmaxf(o.y, 0.f);
                o.z = fmaxf(o.z, 0.f); o.w = fmaxf(o.w, 0.f);
            }
            ((float4*)out)[row * 16 + tc] = o;
        }
    }
}

// ---------------- mean pool per graph (batch is sorted) ----------------
__device__ __forceinline__ int lower_bound_batch(const int* b, int val) {
    int lo = 0, hi = NN;
    while (lo < hi) {
        int mid = (lo + hi) >> 1;
        if (b[mid] < val) lo = mid + 1; else hi = mid;
    }
    return lo;
}

__global__ void pool_kernel(const float* __restrict__ h, const int* __restrict__ batch) {
    int g = blockIdx.x;
    __shared__ int s_lo, s_hi;
    if (threadIdx.x == 0) {
        s_lo = lower_bound_batch(batch, g);
        s_hi = lower_bound_batch(batch, g + 1);
    }
    __syncthreads();
    int lo = s_lo, hi = s_hi;
    int f = threadIdx.x & 63;
    int part = threadIdx.x >> 6;  // 0..3
    float acc = 0.f;
    for (int i = lo + part; i < hi; i += 4) acc += h[i * 64 + f];
    __shared__ float sh[4][64];
    sh[part][f] = acc;
    __syncthreads();
    if (part == 0) {
        float s = sh[0][f] + sh[1][f] + sh[2][f] + sh[3][f];
        float cnt = (float)(hi - lo);
        g_pool[g * 64 + f] = s / fmaxf(cnt, 1.f);
    }
}

// ---------------- final MLP: [64,64]@[64,32]+relu -> @[32,10] ----------------
__global__ void mlp_kernel(const float* __restrict__ Wl1, const float* __restrict__ bl1,
                           const float* __restrict__ Wl2, const float* __restrict__ bl2,
                           float* __restrict__ out) {
    __shared__ float sp[GG * 64];
    __shared__ float sh1[GG * 32];
    int tid = threadIdx.x;
    for (int i = tid; i < GG * 64; i += 256) sp[i] = g_pool[i];
    __syncthreads();
    for (int i = tid; i < GG * 32; i += 256) {
        int g = i >> 5, c = i & 31;
        float s = bl1[c];
        #pragma unroll 8
        for (int k = 0; k < 64; k++) s += sp[g * 64 + k] * Wl1[k * 32 + c];
        sh1[i] = fmaxf(s, 0.f);
    }
    __syncthreads();
    for (int i = tid; i < GG * CC; i += 256) {
        int g = i / CC, c = i % CC;
        float s = bl2[c];
        #pragma unroll
        for (int k = 0; k < 32; k++) s += sh1[g * 32 + k] * Wl2[k * CC + c];
        out[i] = s;
    }
}

// ---------------- launcher ----------------
extern "C" void kernel_launch(void* const* d_in, const int* in_sizes, int n_in,
                              void* d_out, int out_size) {
    const float* x    = (const float*)d_in[0];
    const int*   ei   = (const int*)d_in[1];
    const float* attr = (const float*)d_in[2];
    const int*   bat  = (const int*)d_in[3];
    const float* W1 = (const float*)d_in[4];
    const float* b1 = (const float*)d_in[5];
    const float* W2 = (const float*)d_in[6];
    const float* b2 = (const float*)d_in[7];
    const float* W3 = (const float*)d_in[8];
    const float* b3 = (const float*)d_in[9];
    const float* Wl1 = (const float*)d_in[10];
    const float* bl1 = (const float*)d_in[11];
    const float* Wl2 = (const float*)d_in[12];
    const float* bl2 = (const float*)d_in[13];
    float* out = (float*)d_out;

    float *T1, *H0, *H1;
    void* zp;
    cudaGetSymbolAddress((void**)&T1, g_T1);
    cudaGetSymbolAddress((void**)&H0, g_H0);
    cudaGetSymbolAddress((void**)&H1, g_H1);
    cudaGetSymbolAddress(&zp, g_zero);

    const int SMEM = (12288 + 3 * 4096) * (int)sizeof(float);  // 98304
    cudaFuncSetAttribute(gemmf_kernel<true>,  cudaFuncAttributeMaxDynamicSharedMemorySize, SMEM);
    cudaFuncSetAttribute(gemmf_kernel<false>, cudaFuncAttributeMaxDynamicSharedMemorySize, SMEM);

    const int NB_E = (EE + 255) / 256;
    const int NB_P = (NN + 7) / 8;        // warp per row, 8 warps/block
    const int NB_G = (NN + 63) / 64;      // gemm blocks

    cudaMemsetAsync(zp, 0, ZERO_BYTES);
    deg_kernel<<<NB_E, 256>>>(ei, attr);
    scan_kernel<<<NBLK, 1024>>>();
    fill_kernel<<<NB_E, 256>>>(ei, attr);

    // Layer 1
    prop_kernel<<<NB_P, 256>>>(x, T1);
    gemmf_kernel<true><<<NB_G, 256, SMEM>>>(x, T1, W1, b1, H0);
    // Layer 2
    prop_kernel<<<NB_P, 256>>>(H0, T1);
    gemmf_kernel<true><<<NB_G, 256, SMEM>>>(H0, T1, W2, b2, H1);
    // Layer 3
    prop_kernel<<<NB_P, 256>>>(H1, T1);
    gemmf_kernel<false><<<NB_G, 256, SMEM>>>(H1, T1, W3, b3, H0);

    pool_kernel<<<GG, 256>>>(H0, bat);
    mlp_kernel<<<1, 256>>>(Wl1, bl1, Wl2, bl2, out);
}

// round 6
// speedup vs baseline: 1.0898x; 1.0898x over previous
#include <cuda_runtime.h>

#define NN 50000
#define EE 800000
#define F 64
#define GG 64
#define CC 10
#define NBLK 49   // ceil(NN/1024)

typedef unsigned long long ull;

// ---------------- scratch (device globals; no allocation allowed) ----------------
// zero-region: [wdeg: NN floats][degcnt: NN ints][scan state: NBLK ull]
#define WDEG_OFF   0
#define DEGCNT_OFF (NN * 4)
#define STATE_OFF  (2 * NN * 4)
#define ZERO_BYTES (STATE_OFF + 64 * 8)
__device__ __align__(16) unsigned char g_zero[ZERO_BYTES];

__device__ __align__(16) float g_dinv[NN];
__device__ __align__(16) int   g_rowptr[NN + 1];
__device__ __align__(16) int   g_fill[NN];
__device__ __align__(16) int2  g_edges[EE];      // (col, bitcast(norm)) sorted by row
__device__ __align__(16) float g_T1[NN * F];
__device__ __align__(16) float g_T2[NN * F];
__device__ __align__(16) float g_H0[NN * F];
__device__ __align__(16) float g_H1[NN * F];
__device__ __align__(16) float g_pool[GG * F];

// ---------------- packed f32x2 helpers ----------------
__device__ __forceinline__ void fma2(ull& d, ull a, ull b) {
    asm("fma.rn.f32x2 %0, %1, %2, %0;" : "+l"(d) : "l"(a), "l"(b));
}
__device__ __forceinline__ ull pk2(float lo, float hi) {
    ull r;
    asm("mov.b64 %0, {%1, %2};" : "=l"(r) : "f"(lo), "f"(hi));
    return r;
}
__device__ __forceinline__ float2 unpk2(ull v) {
    float2 r;
    asm("mov.b64 {%0, %1}, %2;" : "=f"(r.x), "=f"(r.y) : "l"(v));
    return r;
}

// ---------------- build ----------------
__global__ void deg_kernel(const int* __restrict__ ei, const float* __restrict__ attr) {
    float* wdeg = (float*)(g_zero + WDEG_OFF);
    int* degcnt = (int*)(g_zero + DEGCNT_OFF);
    int e = blockIdx.x * blockDim.x + threadIdx.x;
    if (e < EE) {
        int r = ei[e];
        atomicAdd(&wdeg[r], attr[e]);
        atomicAdd(&degcnt[r], 1);
    }
}

// Single-kernel scan: block-local scan + publish partial + sum-all-predecessors.
// Fuses dinv, rowptr, fill init. 49 blocks x 1024 (all resident in wave 1).
__global__ void scan_kernel() {
    float* wdeg = (float*)(g_zero + WDEG_OFF);
    int* degcnt = (int*)(g_zero + DEGCNT_OFF);
    volatile ull* state = (volatile ull*)(g_zero + STATE_OFF);

    int tid = threadIdx.x;
    int b = blockIdx.x;
    int i = b * 1024 + tid;
    int v = (i < NN) ? degcnt[i] : 0;

    if (i < NN) {
        float d = wdeg[i];
        g_dinv[i] = (d > 0.f) ? rsqrtf(d) : 0.f;
    }

    int lane = tid & 31, wid = tid >> 5;
    int x = v;
    #pragma unroll
    for (int o = 1; o < 32; o <<= 1) {
        int y = __shfl_up_sync(0xFFFFFFFFu, x, o);
        if (lane >= o) x += y;
    }
    __shared__ int ws[32];
    __shared__ int s_prefix;
    if (lane == 31) ws[wid] = x;
    __syncthreads();
    if (wid == 0) {
        int s = ws[lane];
        #pragma unroll
        for (int o = 1; o < 32; o <<= 1) {
            int y = __shfl_up_sync(0xFFFFFFFFu, s, o);
            if (lane >= o) s += y;
        }
        ws[lane] = s;
    }
    __syncthreads();
    int blocksum = ws[31];

    if (tid == 0) {
        atomicExch((ull*)&state[b], (1ull << 32) | (unsigned)blocksum);
    }
    if (tid < 32) {
        int acc = 0;
        for (int p = tid; p < b; p += 32) {
            ull sv;
            do { sv = state[p]; } while ((sv >> 32) == 0);
            acc += (int)(unsigned)sv;
        }
        #pragma unroll
        for (int o = 16; o > 0; o >>= 1) acc += __shfl_down_sync(0xFFFFFFFFu, acc, o);
        if (tid == 0) s_prefix = acc;
    }
    __syncthreads();

    int excl = x - v + (wid > 0 ? ws[wid - 1] : 0);
    if (i < NN) {
        int r = excl + s_prefix;
        g_rowptr[i] = r;
        g_fill[i]   = r;
    }
    if (b == 0 && tid == 0) g_rowptr[NN] = EE;
}

__global__ void fill_kernel(const int* __restrict__ ei, const float* __restrict__ attr) {
    int e = blockIdx.x * blockDim.x + threadIdx.x;
    if (e < EE) {
        int r = ei[e];
        int c = ei[EE + e];
        float w = -attr[e] * g_dinv[r] * g_dinv[c];
        int pos = atomicAdd(&g_fill[r], 1);
        g_edges[pos] = make_int2(c, __float_as_int(w));
    }
}

// ---------------- sparse propagation: HALF-WARP per row, float4 lanes ----------------
// 16 lanes x float4 = 64 floats = one row. Each warp processes 2 rows concurrently.
// MODE 0: out = S*in        MODE 1: out = 2*S*in - sub
template <int MODE>
__global__ void prop_kernel(const float* __restrict__ in, float* __restrict__ out,
                            const float* __restrict__ sub) {
    int idx = blockIdx.x * blockDim.x + threadIdx.x;
    int row = idx >> 4;
    if (row >= NN) return;
    int l = idx & 15;
    int s = g_rowptr[row], e = g_rowptr[row + 1];
    const float4* in4 = (const float4*)in;

    float4 A = make_float4(0.f, 0.f, 0.f, 0.f);
    float4 B = make_float4(0.f, 0.f, 0.f, 0.f);
    float4 Cq = make_float4(0.f, 0.f, 0.f, 0.f);
    float4 D = make_float4(0.f, 0.f, 0.f, 0.f);
    int j = s;
    for (; j + 4 <= e; j += 4) {
        int2 e0 = g_edges[j];
        int2 e1 = g_edges[j + 1];
        int2 e2 = g_edges[j + 2];
        int2 e3 = g_edges[j + 3];
        float4 v0 = in4[e0.x * 16 + l];
        float4 v1 = in4[e1.x * 16 + l];
        float4 v2 = in4[e2.x * 16 + l];
        float4 v3 = in4[e3.x * 16 + l];
        float w0 = __int_as_float(e0.y);
        float w1 = __int_as_float(e1.y);
        float w2 = __int_as_float(e2.y);
        float w3 = __int_as_float(e3.y);
        A.x = fmaf(w0, v0.x, A.x); A.y = fmaf(w0, v0.y, A.y);
        A.z = fmaf(w0, v0.z, A.z); A.w = fmaf(w0, v0.w, A.w);
        B.x = fmaf(w1, v1.x, B.x); B.y = fmaf(w1, v1.y, B.y);
        B.z = fmaf(w1, v1.z, B.z); B.w = fmaf(w1, v1.w, B.w);
        Cq.x = fmaf(w2, v2.x, Cq.x); Cq.y = fmaf(w2, v2.y, Cq.y);
        Cq.z = fmaf(w2, v2.z, Cq.z); Cq.w = fmaf(w2, v2.w, Cq.w);
        D.x = fmaf(w3, v3.x, D.x); D.y = fmaf(w3, v3.y, D.y);
        D.z = fmaf(w3, v3.z, D.z); D.w = fmaf(w3, v3.w, D.w);
    }
    for (; j < e; j++) {
        int2 ed = g_edges[j];
        float4 v = in4[ed.x * 16 + l];
        float w = __int_as_float(ed.y);
        A.x = fmaf(w, v.x, A.x); A.y = fmaf(w, v.y, A.y);
        A.z = fmaf(w, v.z, A.z); A.w = fmaf(w, v.w, A.w);
    }
    float4 r;
    r.x = (A.x + B.x) + (Cq.x + D.x);
    r.y = (A.y + B.y) + (Cq.y + D.y);
    r.z = (A.z + B.z) + (Cq.z + D.z);
    r.w = (A.w + B.w) + (Cq.w + D.w);

    if (MODE == 1) {
        float4 sv = ((const float4*)sub)[row * 16 + l];
        r.x = 2.f * r.x - sv.x;
        r.y = 2.f * r.y - sv.y;
        r.z = 2.f * r.z - sv.z;
        r.w = 2.f * r.w - sv.w;
    }
    ((float4*)out)[row * 16 + l] = r;
}

// ---------------- fused 3-matrix GEMM with packed f32x2 FMA ----------------
// out = relu?(x0@W[0] + x1@W[1] + x2@W[2] + b)
// block: 64 rows x 64 cols, 256 threads, thread tile 4x4
template <bool RELU>
__global__ __launch_bounds__(256, 2) void gemm3_kernel(
    const float* __restrict__ x0, const float* __restrict__ x1, const float* __restrict__ x2,
    const float* __restrict__ W, const float* __restrict__ b, float* __restrict__ out) {
    extern __shared__ float smem[];
    float* sW = smem;             // 3*64*64
    float* sX = smem + 12288;     // 3*64*64
    int tid = threadIdx.x;
    int row0 = blockIdx.x * 64;

    {
        float4* d = (float4*)sW;
        const float4* g = (const float4*)W;
        #pragma unroll
        for (int i = tid; i < 3 * 1024; i += 256) d[i] = g[i];
    }
    {
        for (int m = 0; m < 3; m++) {
            const float* src = (m == 0) ? x0 : (m == 1) ? x1 : x2;
            float4* d = (float4*)(sX + m * 4096);
            const float4* g = (const float4*)src;
            for (int i = tid; i < 1024; i += 256) {
                int r = i >> 4, c = i & 15;
                int row = row0 + r;
                d[i] = (row < NN) ? g[row * 16 + c] : make_float4(0.f, 0.f, 0.f, 0.f);
            }
        }
    }
    __syncthreads();

    int tc = tid & 15;
    int tr = tid >> 4;

    ull accA[4], accB[4];
    #pragma unroll
    for (int i = 0; i < 4; i++) { accA[i] = 0ull; accB[i] = 0ull; }

    const ull* wp = (const ull*)sW;  // mat m at m*2048, row k at k*32, col-pair tc*2
    const float* X0 = sX;
    const float* X1 = sX + 4096;
    const float* X2 = sX + 8192;

    #pragma unroll 4
    for (int k = 0; k < 64; k += 4) {
        float4 a0[4], a1[4], a2[4];
        #pragma unroll
        for (int i = 0; i < 4; i++) {
            int r = tr * 4 + i;
            a0[i] = *(const float4*)(X0 + r * 64 + k);
            a1[i] = *(const float4*)(X1 + r * 64 + k);
            a2[i] = *(const float4*)(X2 + r * 64 + k);
        }
        #pragma unroll
        for (int j = 0; j < 4; j++) {
            int wi = (k + j) * 32 + tc * 2;
            ull w0xy = wp[wi],        w0zw = wp[wi + 1];
            ull w1xy = wp[2048 + wi], w1zw = wp[2048 + wi + 1];
            ull w2xy = wp[4096 + wi], w2zw = wp[4096 + wi + 1];
            #pragma unroll
            for (int i = 0; i < 4; i++) {
                float p = ((const float*)&a0[i])[j];
                float q = ((const float*)&a1[i])[j];
                float t = ((const float*)&a2[i])[j];
                ull pp = pk2(p, p);
                ull qq = pk2(q, q);
                ull tt = pk2(t, t);
                fma2(accA[i], w0xy, pp);
                fma2(accB[i], w0zw, pp);
                fma2(accA[i], w1xy, qq);
                fma2(accB[i], w1zw, qq);
                fma2(accA[i], w2xy, tt);
                fma2(accB[i], w2zw, tt);
            }
        }
    }

    float4 bias = ((const float4*)b)[tc];
    #pragma unroll
    for (int i = 0; i < 4; i++) {
        int row = row0 + tr * 4 + i;
        if (row < NN) {
            float2 lo = unpk2(accA[i]);
            float2 hi = unpk2(accB[i]);
            float4 o;
            o.x = lo.x + bias.x;
            o.y = lo.y + bias.y;
            o.z = hi.x + bias.z;
            o.w = hi.y + bias.w;
            if (RELU) {
                o.x = fmaxf(o.x, 0.f); o.y = fmaxf(o.y, 0.f);
                o.z = fmaxf(o.z, 0.f); o.w = fmaxf(o.w, 0.f);
            }
            ((float4*)out)[row * 16 + tc] = o;
        }
    }
}

// ---------------- mean pool per graph (batch is sorted) ----------------
__device__ __forceinline__ int lower_bound_batch(const int* b, int val) {
    int lo = 0, hi = NN;
    while (lo < hi) {
        int mid = (lo + hi) >> 1;
        if (b[mid] < val) lo = mid + 1; else hi = mid;
    }
    return lo;
}

__global__ void pool_kernel(const float* __restrict__ h, const int* __restrict__ batch) {
    int g = blockIdx.x;
    __shared__ int s_lo, s_hi;
    if (threadIdx.x == 0) {
        s_lo = lower_bound_batch(batch, g);
        s_hi = lower_bound_batch(batch, g + 1);
    }
    __syncthreads();
    int lo = s_lo, hi = s_hi;
    int f = threadIdx.x & 63;
    int part = threadIdx.x >> 6;
    float acc = 0.f;
    for (int i = lo + part; i < hi; i += 4) acc += h[i * 64 + f];
    __shared__ float sh[4][64];
    sh[part][f] = acc;
    __syncthreads();
    if (part == 0) {
        float s = sh[0][f] + sh[1][f] + sh[2][f] + sh[3][f];
        float cnt = (float)(hi - lo);
        g_pool[g * 64 + f] = s / fmaxf(cnt, 1.f);
    }
}

// ---------------- final MLP ----------------
__global__ void mlp_kernel(const float* __restrict__ Wl1, const float* __restrict__ bl1,
                           const float* __restrict__ Wl2, const float* __restrict__ bl2,
                           float* __restrict__ out) {
    __shared__ float sp[GG * 64];
    __shared__ float sh1[GG * 32];
    int tid = threadIdx.x;
    for (int i = tid; i < GG * 64; i += 256) sp[i] = g_pool[i];
    __syncthreads();
    for (int i = tid; i < GG * 32; i += 256) {
        int g = i >> 5, c = i & 31;
        float s = bl1[c];
        #pragma unroll 8
        for (int k = 0; k < 64; k++) s += sp[g * 64 + k] * Wl1[k * 32 + c];
        sh1[i] = fmaxf(s, 0.f);
    }
    __syncthreads();
    for (int i = tid; i < GG * CC; i += 256) {
        int g = i / CC, c = i % CC;
        float s = bl2[c];
        #pragma unroll
        for (int k = 0; k < 32; k++) s += sh1[g * 32 + k] * Wl2[k * CC + c];
        out[i] = s;
    }
}

// ---------------- launcher ----------------
extern "C" void kernel_launch(void* const* d_in, const int* in_sizes, int n_in,
                              void* d_out, int out_size) {
    const float* x    = (const float*)d_in[0];
    const int*   ei   = (const int*)d_in[1];
    const float* attr = (const float*)d_in[2];
    const int*   bat  = (const int*)d_in[3];
    const float* W1 = (const float*)d_in[4];
    const float* b1 = (const float*)d_in[5];
    const float* W2 = (const float*)d_in[6];
    const float* b2 = (const float*)d_in[7];
    const float* W3 = (const float*)d_in[8];
    const float* b3 = (const float*)d_in[9];
    const float* Wl1 = (const float*)d_in[10];
    const float* bl1 = (const float*)d_in[11];
    const float* Wl2 = (const float*)d_in[12];
    const float* bl2 = (const float*)d_in[13];
    float* out = (float*)d_out;

    float *T1, *T2, *H0, *H1;
    void* zp;
    cudaGetSymbolAddress((void**)&T1, g_T1);
    cudaGetSymbolAddress((void**)&T2, g_T2);
    cudaGetSymbolAddress((void**)&H0, g_H0);
    cudaGetSymbolAddress((void**)&H1, g_H1);
    cudaGetSymbolAddress(&zp, g_zero);

    const int SMEM = (12288 + 12288) * (int)sizeof(float);  // 98304
    cudaFuncSetAttribute(gemm3_kernel<true>,  cudaFuncAttributeMaxDynamicSharedMemorySize, SMEM);
    cudaFuncSetAttribute(gemm3_kernel<false>, cudaFuncAttributeMaxDynamicSharedMemorySize, SMEM);

    const int NB_E = (EE + 255) / 256;
    const int NB_P = (NN * 16 + 255) / 256;  // 16 threads per row
    const int NB_G = (NN + 63) / 64;

    cudaMemsetAsync(zp, 0, ZERO_BYTES);
    deg_kernel<<<NB_E, 256>>>(ei, attr);
    scan_kernel<<<NBLK, 1024>>>();
    fill_kernel<<<NB_E, 256>>>(ei, attr);

    // Layer 1
    prop_kernel<0><<<NB_P, 256>>>(x, T1, nullptr);
    prop_kernel<1><<<NB_P, 256>>>(T1, T2, x);
    gemm3_kernel<true><<<NB_G, 256, SMEM>>>(x, T1, T2, W1, b1, H0);
    // Layer 2
    prop_kernel<0><<<NB_P, 256>>>(H0, T1, nullptr);
    prop_kernel<1><<<NB_P, 256>>>(T1, T2, H0);
    gemm3_kernel<true><<<NB_G, 256, SMEM>>>(H0, T1, T2, W2, b2, H1);
    // Layer 3
    prop_kernel<0><<<NB_P, 256>>>(H1, T1, nullptr);
    prop_kernel<1><<<NB_P, 256>>>(T1, T2, H1);
    gemm3_kernel<false><<<NB_G, 256, SMEM>>>(H1, T1, T2, W3, b3, H0);

    pool_kernel<<<GG, 256>>>(H0, bat);
    mlp_kernel<<<1, 256>>>(Wl1, bl1, Wl2, bl2, out);
}